// round 16
// baseline (speedup 1.0000x reference)
#include <cuda_runtime.h>

// Problem constants (fixed by reference: (3,x)-regular-column LDPC)
#define N_VAR  1152
#define M_CHK  576
#define E_EDGE 3456   // N_VAR * 3
#define BATCH  16
#define MAXD   32     // max check degree (lane-mapped)
#define MAX_IT 8      // provisioned launches; guarded by device-read bp_iter_num
#define SLOT_CAP 576  // worst-case warp-slots per batch item

// Scratch (no allocation) — re-derived every launch (graph-replay safe).
__device__ int   g_p_r2l[E_EDGE];            // col-major edge -> row-major index
__device__ int   g_p_l2r[E_EDGE];            // inverse permutation
__device__ int   g_chk_mem[M_CHK * MAXD];    // per check: member col-major edges, ASCENDING
__device__ int   g_chk_d[M_CHK];             // check degree
__device__ int   g_slot_info[SLOT_CAP * 32]; // per warp-slot, per lane: edge|base<<12|d<<17
__device__ int   g_nslots;                   // used warp-slots per batch item
__device__ int   g_sel_y;                    // 1 if en1 is H_xe_v_sumc_to_y
__device__ float g_vsr[2][BATCH * E_EDGE];   // ping-pong C->V messages, col-major index

// ---------------------------------------------------------------------------
// Kernel 1: classify the two [E*N] inputs. H_x_to_xe0[e, e/3]==1 for ALL e.
// ---------------------------------------------------------------------------
__global__ void probe_en_kernel(const float* __restrict__ en0,
                                const float* __restrict__ en1) {
    __shared__ int w0[32], w1[32];
    int tid = threadIdx.x;
    int c0 = 0, c1 = 0;
    for (int e = tid; e < E_EDGE; e += 1024) {
        size_t off = (size_t)e * N_VAR + e / 3;
        c0 += (en0[off] == 1.0f) ? 1 : 0;
        c1 += (en1[off] == 1.0f) ? 1 : 0;
    }
    for (int o = 16; o > 0; o >>= 1) {
        c0 += __shfl_down_sync(0xffffffff, c0, o);
        c1 += __shfl_down_sync(0xffffffff, c1, o);
    }
    if ((tid & 31) == 0) { w0[tid >> 5] = c0; w1[tid >> 5] = c1; }
    __syncthreads();
    if (tid == 0) {
        int t0 = 0, t1 = 0;
        for (int w = 0; w < 32; ++w) { t0 += w0[w]; t1 += w1[w]; }
        g_sel_y = (t1 == E_EDGE && t0 != E_EDGE) ? 0 : 1;   // other one is Hy
    }
}

// ---------------------------------------------------------------------------
// Kernel 2: extract p_r2l / p_l2r from H_xe_v_sumc_to_y [N_VAR, E].
// Row v has exactly 3 ones at ascending columns = p_r2l[3v..3v+2].
// ---------------------------------------------------------------------------
__global__ void extract_perm_kernel(const float* __restrict__ en0,
                                    const float* __restrict__ en1) {
    const float* Hy = g_sel_y ? en1 : en0;
    int v = blockIdx.x;
    __shared__ int idxs[8];
    __shared__ int cnt;
    if (threadIdx.x == 0) { cnt = 0; idxs[0] = 0; idxs[1] = 0; idxs[2] = 0; }
    __syncthreads();

    const float4* row = reinterpret_cast<const float4*>(Hy + (size_t)v * E_EDGE);
    for (int q = threadIdx.x; q < E_EDGE / 4; q += blockDim.x) {
        float4 f = row[q];
        if (f.x != 0.0f) { int p = atomicAdd(&cnt, 1); if (p < 8) idxs[p] = 4 * q + 0; }
        if (f.y != 0.0f) { int p = atomicAdd(&cnt, 1); if (p < 8) idxs[p] = 4 * q + 1; }
        if (f.z != 0.0f) { int p = atomicAdd(&cnt, 1); if (p < 8) idxs[p] = 4 * q + 2; }
        if (f.w != 0.0f) { int p = atomicAdd(&cnt, 1); if (p < 8) idxs[p] = 4 * q + 3; }
    }
    __syncthreads();
    if (threadIdx.x == 0) {
        int a = idxs[0], b = idxs[1], c = idxs[2], t;
        if (a > b) { t = a; a = b; b = t; }
        if (b > c) { t = b; b = c; c = t; }
        if (a > b) { t = a; a = b; b = t; }
        g_p_r2l[3 * v + 0] = a;  g_p_l2r[a] = 3 * v + 0;
        g_p_r2l[3 * v + 1] = b;  g_p_l2r[b] = 3 * v + 1;
        g_p_r2l[3 * v + 2] = c;  g_p_l2r[c] = 3 * v + 2;
    }
}

// ---------------------------------------------------------------------------
// Kernel 3: check groups via E probes (production-validated) + WARP PACKING.
// np.nonzero is row-major => a check's edges are CONTIGUOUS row-major.
// H_sumC_to_V[j-1, p_l2r[j]] != 0  <=>  edge j-1 and j share a check.
// Emits per-check ascending member lists, then greedily bin-packs checks
// into 32-lane warp slots (lane segment [base, base+d)), emitting a packed
// per-lane descriptor: edge | base<<12 | d<<17.
// ---------------------------------------------------------------------------
__global__ void build_groups_kernel(const float* __restrict__ ee0,
                                    const float* __restrict__ ee1) {
    __shared__ unsigned char f0[E_EDGE], f1[E_EDGE];
    __shared__ int tsum[1024];
    __shared__ int cs[M_CHK + 1];
    __shared__ short chk_slot[M_CHK], chk_base[M_CHK];
    __shared__ int w0[32], w1[32];
    __shared__ int sel_c2v, ngroups;
    int tid = threadIdx.x;

    // zero the slot table up front (independent of everything below)
    for (int i = tid; i < SLOT_CAP * 32; i += 1024) g_slot_info[i] = 0;

    int c0 = 0, c1 = 0;
    for (int j = tid; j < E_EDGE; j += 1024) {
        int p0 = 0, p1 = 0;
        if (j > 0) {
            size_t off = (size_t)(j - 1) * E_EDGE + g_p_l2r[j];
            p0 = (ee0[off] != 0.0f) ? 1 : 0;
            p1 = (ee1[off] != 0.0f) ? 1 : 0;
        }
        f0[j] = (unsigned char)p0;
        f1[j] = (unsigned char)p1;
        c0 += p0; c1 += p1;
    }
    for (int o = 16; o > 0; o >>= 1) {
        c0 += __shfl_down_sync(0xffffffff, c0, o);
        c1 += __shfl_down_sync(0xffffffff, c1, o);
    }
    if ((tid & 31) == 0) { w0[tid >> 5] = c0; w1[tid >> 5] = c1; }
    __syncthreads();
    if (tid == 0) {
        int t0 = 0, t1 = 0;
        for (int w = 0; w < 32; ++w) { t0 += w0[w]; t1 += w1[w]; }
        sel_c2v = (t1 > t0) ? 1 : 0;
    }
    __syncthreads();
    const unsigned char* f = sel_c2v ? f1 : f0;

    // prefix scan of "new group" flags (4 per thread)
    int base = tid * 4;
    int loc[4], s = 0;
    #pragma unroll
    for (int m = 0; m < 4; ++m) {
        int j = base + m;
        int v = 0;
        if (j < E_EDGE) v = (j == 0) ? 1 : (f[j] ? 0 : 1);
        loc[m] = v; s += v;
    }
    tsum[tid] = s;
    __syncthreads();
    for (int off = 1; off < 1024; off <<= 1) {
        int add = (tid >= off) ? tsum[tid - off] : 0;
        __syncthreads();
        tsum[tid] += add;
        __syncthreads();
    }
    int run = (tid == 0) ? 0 : tsum[tid - 1];

    if (tid <= M_CHK) cs[tid] = E_EDGE;
    if (tid < M_CHK) g_chk_d[tid] = 0;
    __syncthreads();
    #pragma unroll
    for (int m = 0; m < 4; ++m) {
        int j = base + m;
        if (j < E_EDGE && loc[m]) {
            if (run <= M_CHK) cs[run] = j;
            ++run;
        }
    }
    if (tid == 0) {
        int n = tsum[1023];
        ngroups = (n > M_CHK) ? M_CHK : n;
    }
    __syncthreads();

    // per group: member col-major indices sorted ascending
    for (int g = tid; g < ngroups; g += 1024) {
        int s0 = cs[g], e0 = cs[g + 1];
        int d = e0 - s0;
        if (d > MAXD) d = MAXD;
        int cols[MAXD];
        for (int i = 0; i < d; ++i) cols[i] = g_p_l2r[s0 + i];
        for (int i = 1; i < d; ++i) {
            int key = cols[i], q = i - 1;
            while (q >= 0 && cols[q] > key) { cols[q + 1] = cols[q]; --q; }
            cols[q + 1] = key;
        }
        g_chk_d[g] = d;
        for (int i = 0; i < d; ++i) g_chk_mem[g * MAXD + i] = cols[i];
    }
    __syncthreads();

    // greedy first-fit bin-packing of checks into 32-lane warp slots
    if (tid == 0) {
        int slot = -1, fill = 32;
        int ng = ngroups;
        for (int g = 0; g < ng; ++g) {
            int d = g_chk_d[g];
            if (d < 1) d = 1;            // defensive
            if (fill + d > 32) { ++slot; fill = 0; }
            chk_slot[g] = (short)slot;
            chk_base[g] = (short)fill;
            fill += d;
        }
        g_nslots = slot + 1;
    }
    __syncthreads();

    // emit per-lane packed descriptors
    for (int g = tid; g < ngroups; g += 1024) {
        int d = g_chk_d[g];
        int sl = chk_slot[g], bs = chk_base[g];
        int* dst = g_slot_info + sl * 32 + bs;
        for (int i = 0; i < d; ++i)
            dst[i] = g_chk_mem[g * MAXD + i] | (bs << 12) | (d << 17);
    }
}

// ---------------------------------------------------------------------------
// Helper (identical arithmetic to the passing R10/R15 kernels)
// ---------------------------------------------------------------------------
__device__ __forceinline__ float2 lrk_of(float x) {
    float t = tanhf(0.5f * x);
    float lr = logf(1e-8f + fabsf(t));
    float k = (x < 0.0f) ? 2.0f : ((x > 0.0f) ? 0.0f : 1.0f);
    return make_float2(lr, k);
}

// ---------------------------------------------------------------------------
// Kernel 4 (x MAX_IT): bin-packed warps. Each lane owns one edge of one
// check; checks occupy lane segments [base, base+d) with members ascending.
// Exclude-self sums via segment-relative shuffle broadcast — identical
// values and ascending order as R15 (bit-exact). vsr ping-pongs.
// ---------------------------------------------------------------------------
__global__ void __launch_bounds__(256)
bp_check_kernel(const float* __restrict__ llr,
                const int* __restrict__ iters_p, int it) {
    int iters = iters_p ? iters_p[0] : MAX_IT;
    if (iters < 1 || iters > MAX_IT) iters = MAX_IT;
    if (it >= iters) return;

    int w = (blockIdx.x * 256 + threadIdx.x) >> 5;   // global warp id
    int lane = threadIdx.x & 31;
    int b = w / SLOT_CAP, s = w - b * SLOT_CAP;
    if (s >= g_nslots) return;                       // uniform early exit

    int info = g_slot_info[s * 32 + lane];
    int d    = info >> 17;                           // 0 => idle lane
    int base = (info >> 12) & 31;
    int c    = info & 0xFFF;                         // col-major member edge

    float lkx = 0.0f, lky = 0.0f;
    if (d > 0) {
        int v = c / 3;
        float x = __ldg(&llr[b * N_VAR + v]);
        if (it > 0) {
            int vb = 3 * v, r = c - vb;
            int s1 = vb + ((r == 0) ? 1 : 0);        // ascending siblings
            int s2 = vb + ((r == 2) ? 1 : 2);
            const float* vp = g_vsr[(it - 1) & 1] + (size_t)b * E_EDGE;
            x = x + (vp[s1] + vp[s2]);               // R10 v2c pairing
        }
        float2 lk = lrk_of(x);
        lkx = lk.x; lky = lk.y;
    }

    // exclude-self sums, strictly ascending in-segment order (matmul order)
    int dmax = __reduce_max_sync(0xffffffffu, d);
    int myq = lane - base;
    float slr = 0.0f, skf = 0.0f;
    for (int q = 0; q < dmax; ++q) {
        float vx = __shfl_sync(0xffffffffu, lkx, base + q);
        float vy = __shfl_sync(0xffffffffu, lky, base + q);
        if (q < d && q != myq) { slr += vx; skf += vy; }
    }

    if (d > 0) {
        int sk = (int)skf;   // exact small integer
        // cos(sk*pi/2): exactly +-1 for even sk, 0 for odd
        float cv = (sk & 1) ? 0.0f : ((sk & 2) ? -1.0f : 1.0f);
        float prod = expf(slr) * cv;
        float sg = (prod > 0.0f) ? 1.0f : ((prod < 0.0f) ? -1.0f : 0.0f);
        float pd = prod - 2e-7f * sg;
        float vs = logf((1.0f + pd) / (1.0f - pd + 1e-10f));
        g_vsr[it & 1][(size_t)b * E_EDGE + c] = vs;
    }
}

// ---------------------------------------------------------------------------
// Kernel 5: hard decision. vsr is col-major-indexed; p_r2l ascending per
// variable => (vsr[3v] + vsr[3v+1]) + vsr[3v+2] is R10's decision order.
// Output float 0/1 (dtype lesson of round 9).
// ---------------------------------------------------------------------------
__global__ void bp_decision_kernel(const float* __restrict__ llr,
                                   const int* __restrict__ iters_p,
                                   float* __restrict__ out) {
    int iters = iters_p ? iters_p[0] : MAX_IT;
    if (iters < 1 || iters > MAX_IT) iters = MAX_IT;
    int pb = (iters - 1) & 1;

    int idx = blockIdx.x * blockDim.x + threadIdx.x;
    if (idx >= BATCH * N_VAR) return;
    int b = idx / N_VAR, v = idx - b * N_VAR;
    const float* vp = g_vsr[pb] + (size_t)b * E_EDGE;
    float T = (vp[3 * v] + vp[3 * v + 1]) + vp[3 * v + 2];
    float l = __ldg(&llr[idx]) + T;
    int sgn = (l > 0.0f) ? 1 : ((l < 0.0f) ? -1 : 0);
    out[idx] = (float)((1 - sgn) >> 1);   // 0.0f / 1.0f
}

// ---------------------------------------------------------------------------
// Inputs identified by element count (robust to ordering):
//   18432      -> llr_in [16,1152]
//   3981312 x2 -> H_x_to_xe0 [E,N] / H_xe_v_sumc_to_y [N,E]  (probed)
//   11943936x2 -> H_sumC_to_V / H_sumV_to_C [E,E]            (probed)
//   1          -> bp_iter_num int32
// Output: float32 [16, 1152] (0.0 / 1.0)
// ---------------------------------------------------------------------------
extern "C" void kernel_launch(void* const* d_in, const int* in_sizes, int n_in,
                              void* d_out, int out_size) {
    int idx_llr = -1, idx_it = -1;
    int en[2] = {-1, -1}, ee[2] = {-1, -1};
    int nen = 0, nee = 0;
    for (int i = 0; i < n_in; ++i) {
        int s = in_sizes[i];
        if (s == BATCH * N_VAR) idx_llr = i;
        else if (s == 1) idx_it = i;
        else if (s == E_EDGE * N_VAR) { if (nen < 2) en[nen] = i; nen++; }
        else if (s == E_EDGE * E_EDGE) { if (nee < 2) ee[nee] = i; nee++; }
    }
    if (idx_llr < 0) idx_llr = 0;
    if (en[0] < 0) en[0] = 1;
    if (en[1] < 0) en[1] = 4;
    if (ee[0] < 0) ee[0] = 2;
    if (ee[1] < 0) ee[1] = 3;

    const float* llr = (const float*)d_in[idx_llr];
    const float* en0 = (const float*)d_in[en[0]];
    const float* en1 = (const float*)d_in[en[1]];
    const float* ee0 = (const float*)d_in[ee[0]];
    const float* ee1 = (const float*)d_in[ee[1]];
    const int* iters = (idx_it >= 0) ? (const int*)d_in[idx_it] : (const int*)0;
    float* out = (float*)d_out;

    probe_en_kernel<<<1, 1024>>>(en0, en1);
    extract_perm_kernel<<<N_VAR, 128>>>(en0, en1);
    build_groups_kernel<<<1, 1024>>>(ee0, ee1);

    const int GW = (BATCH * SLOT_CAP * 32) / 256;   // 1152 blocks (early-exit slots)
    for (int it = 0; it < MAX_IT; ++it)
        bp_check_kernel<<<GW, 256>>>(llr, iters, it);
    bp_decision_kernel<<<(BATCH * N_VAR + 255) / 256, 256>>>(llr, iters, out);
}

// round 17
// speedup vs baseline: 1.1034x; 1.1034x over previous
#include <cuda_runtime.h>

// Problem constants (fixed by reference: (3,x)-regular-column LDPC)
#define N_VAR  1152
#define M_CHK  576
#define E_EDGE 3456   // N_VAR * 3
#define BATCH  16
#define HBATCH 8      // batch pairs: warp handles (b, b+8)
#define MAXD   32     // max check degree (lane-mapped)
#define MAX_IT 8      // provisioned launches; guarded by device-read bp_iter_num

// Scratch (no allocation) — re-derived every launch (graph-replay safe).
__device__ int   g_p_r2l[E_EDGE];          // col-major edge -> row-major index
__device__ int   g_p_l2r[E_EDGE];          // inverse permutation
__device__ int   g_chk_mem[M_CHK * MAXD];  // per check: member col-major edges, ASCENDING
__device__ int   g_chk_d[M_CHK];           // check degree
__device__ int   g_sel_y;                  // 1 if en1 is H_xe_v_sumc_to_y
__device__ float g_vsr[2][BATCH * E_EDGE]; // ping-pong C->V messages, col-major index

// ---------------------------------------------------------------------------
// Kernel 1: classify the two [E*N] inputs. H_x_to_xe0[e, e/3]==1 for ALL e.
// ---------------------------------------------------------------------------
__global__ void probe_en_kernel(const float* __restrict__ en0,
                                const float* __restrict__ en1) {
    __shared__ int w0[32], w1[32];
    int tid = threadIdx.x;
    int c0 = 0, c1 = 0;
    for (int e = tid; e < E_EDGE; e += 1024) {
        size_t off = (size_t)e * N_VAR + e / 3;
        c0 += (en0[off] == 1.0f) ? 1 : 0;
        c1 += (en1[off] == 1.0f) ? 1 : 0;
    }
    for (int o = 16; o > 0; o >>= 1) {
        c0 += __shfl_down_sync(0xffffffff, c0, o);
        c1 += __shfl_down_sync(0xffffffff, c1, o);
    }
    if ((tid & 31) == 0) { w0[tid >> 5] = c0; w1[tid >> 5] = c1; }
    __syncthreads();
    if (tid == 0) {
        int t0 = 0, t1 = 0;
        for (int w = 0; w < 32; ++w) { t0 += w0[w]; t1 += w1[w]; }
        g_sel_y = (t1 == E_EDGE && t0 != E_EDGE) ? 0 : 1;   // other one is Hy
    }
}

// ---------------------------------------------------------------------------
// Kernel 2: extract p_r2l / p_l2r from H_xe_v_sumc_to_y [N_VAR, E].
// Row v has exactly 3 ones at ascending columns = p_r2l[3v..3v+2].
// ---------------------------------------------------------------------------
__global__ void extract_perm_kernel(const float* __restrict__ en0,
                                    const float* __restrict__ en1) {
    const float* Hy = g_sel_y ? en1 : en0;
    int v = blockIdx.x;
    __shared__ int idxs[8];
    __shared__ int cnt;
    if (threadIdx.x == 0) { cnt = 0; idxs[0] = 0; idxs[1] = 0; idxs[2] = 0; }
    __syncthreads();

    const float4* row = reinterpret_cast<const float4*>(Hy + (size_t)v * E_EDGE);
    for (int q = threadIdx.x; q < E_EDGE / 4; q += blockDim.x) {
        float4 f = row[q];
        if (f.x != 0.0f) { int p = atomicAdd(&cnt, 1); if (p < 8) idxs[p] = 4 * q + 0; }
        if (f.y != 0.0f) { int p = atomicAdd(&cnt, 1); if (p < 8) idxs[p] = 4 * q + 1; }
        if (f.z != 0.0f) { int p = atomicAdd(&cnt, 1); if (p < 8) idxs[p] = 4 * q + 2; }
        if (f.w != 0.0f) { int p = atomicAdd(&cnt, 1); if (p < 8) idxs[p] = 4 * q + 3; }
    }
    __syncthreads();
    if (threadIdx.x == 0) {
        int a = idxs[0], b = idxs[1], c = idxs[2], t;
        if (a > b) { t = a; a = b; b = t; }
        if (b > c) { t = b; b = c; c = t; }
        if (a > b) { t = a; a = b; b = t; }
        g_p_r2l[3 * v + 0] = a;  g_p_l2r[a] = 3 * v + 0;
        g_p_r2l[3 * v + 1] = b;  g_p_l2r[b] = 3 * v + 1;
        g_p_r2l[3 * v + 2] = c;  g_p_l2r[c] = 3 * v + 2;
    }
}

// ---------------------------------------------------------------------------
// Kernel 3: check groups via E probes (production-validated):
// np.nonzero is row-major => a check's edges are CONTIGUOUS row-major.
// H_sumC_to_V[j-1, p_l2r[j]] != 0  <=>  edge j-1 and j share a check.
// Probes also classify the EE pair. Emits per-check member lists sorted
// ascending by col-major index (the matmul accumulation order).
// ---------------------------------------------------------------------------
__global__ void build_groups_kernel(const float* __restrict__ ee0,
                                    const float* __restrict__ ee1) {
    __shared__ unsigned char f0[E_EDGE], f1[E_EDGE];
    __shared__ int tsum[1024];
    __shared__ int cs[M_CHK + 1];
    __shared__ int w0[32], w1[32];
    __shared__ int sel_c2v, ngroups;
    int tid = threadIdx.x;

    int c0 = 0, c1 = 0;
    for (int j = tid; j < E_EDGE; j += 1024) {
        int p0 = 0, p1 = 0;
        if (j > 0) {
            size_t off = (size_t)(j - 1) * E_EDGE + g_p_l2r[j];
            p0 = (ee0[off] != 0.0f) ? 1 : 0;
            p1 = (ee1[off] != 0.0f) ? 1 : 0;
        }
        f0[j] = (unsigned char)p0;
        f1[j] = (unsigned char)p1;
        c0 += p0; c1 += p1;
    }
    for (int o = 16; o > 0; o >>= 1) {
        c0 += __shfl_down_sync(0xffffffff, c0, o);
        c1 += __shfl_down_sync(0xffffffff, c1, o);
    }
    if ((tid & 31) == 0) { w0[tid >> 5] = c0; w1[tid >> 5] = c1; }
    __syncthreads();
    if (tid == 0) {
        int t0 = 0, t1 = 0;
        for (int w = 0; w < 32; ++w) { t0 += w0[w]; t1 += w1[w]; }
        sel_c2v = (t1 > t0) ? 1 : 0;
    }
    __syncthreads();
    const unsigned char* f = sel_c2v ? f1 : f0;

    // prefix scan of "new group" flags (4 per thread)
    int base = tid * 4;
    int loc[4], s = 0;
    #pragma unroll
    for (int m = 0; m < 4; ++m) {
        int j = base + m;
        int v = 0;
        if (j < E_EDGE) v = (j == 0) ? 1 : (f[j] ? 0 : 1);
        loc[m] = v; s += v;
    }
    tsum[tid] = s;
    __syncthreads();
    for (int off = 1; off < 1024; off <<= 1) {
        int add = (tid >= off) ? tsum[tid - off] : 0;
        __syncthreads();
        tsum[tid] += add;
        __syncthreads();
    }
    int run = (tid == 0) ? 0 : tsum[tid - 1];

    if (tid <= M_CHK) cs[tid] = E_EDGE;
    if (tid < M_CHK) g_chk_d[tid] = 0;
    __syncthreads();
    #pragma unroll
    for (int m = 0; m < 4; ++m) {
        int j = base + m;
        if (j < E_EDGE && loc[m]) {
            if (run <= M_CHK) cs[run] = j;
            ++run;
        }
    }
    if (tid == 0) {
        int n = tsum[1023];
        ngroups = (n > M_CHK) ? M_CHK : n;
    }
    __syncthreads();

    // per group: member col-major indices sorted ascending
    for (int g = tid; g < ngroups; g += 1024) {
        int s0 = cs[g], e0 = cs[g + 1];
        int d = e0 - s0;
        if (d > MAXD) d = MAXD;
        int cols[MAXD];
        for (int i = 0; i < d; ++i) cols[i] = g_p_l2r[s0 + i];
        for (int i = 1; i < d; ++i) {
            int key = cols[i], q = i - 1;
            while (q >= 0 && cols[q] > key) { cols[q + 1] = cols[q]; --q; }
            cols[q + 1] = key;
        }
        g_chk_d[g] = d;
        for (int i = 0; i < d; ++i) g_chk_mem[g * MAXD + i] = cols[i];
    }
}

// ---------------------------------------------------------------------------
// Helpers (identical arithmetic to the passing R10/R15 kernels)
// ---------------------------------------------------------------------------
__device__ __forceinline__ float2 lrk_of(float x) {
    float t = tanhf(0.5f * x);
    float lr = logf(1e-8f + fabsf(t));
    float k = (x < 0.0f) ? 2.0f : ((x > 0.0f) ? 0.0f : 1.0f);
    return make_float2(lr, k);
}

__device__ __forceinline__ float vsr_tail(float slr, float skf) {
    int sk = (int)skf;   // exact small integer
    // cos(sk*pi/2): exactly +-1 for even sk, 0 for odd
    float cv = (sk & 1) ? 0.0f : ((sk & 2) ? -1.0f : 1.0f);
    float prod = expf(slr) * cv;
    float sg = (prod > 0.0f) ? 1.0f : ((prod < 0.0f) ? -1.0f : 0.0f);
    float pd = prod - 2e-7f * sg;
    return logf((1.0f + pd) / (1.0f - pd + 1e-10f));
}

// ---------------------------------------------------------------------------
// Kernel 4 (x MAX_IT): ONE WARP PER (batch-pair, check). Lane i owns the
// check's i-th member edge (ascending col-major) for BOTH batch items b and
// b+8 — two independent chains per warp (ILP2) sharing all index math.
// Exclude-self sums via shuffle broadcast in strictly ascending member
// order — bit-identical to the passing R15 kernel per batch item.
// ---------------------------------------------------------------------------
__global__ void __launch_bounds__(256)
bp_check_kernel(const float* __restrict__ llr,
                const int* __restrict__ iters_p, int it) {
    int iters = iters_p ? iters_p[0] : MAX_IT;
    if (iters < 1 || iters > MAX_IT) iters = MAX_IT;
    if (it >= iters) return;

    int w = (blockIdx.x * 256 + threadIdx.x) >> 5;   // global warp id
    int lane = threadIdx.x & 31;
    int bh = w / M_CHK, g = w - bh * M_CHK;          // bh in [0, HBATCH)
    if (bh >= HBATCH) return;
    const int b0 = bh, b1 = bh + HBATCH;

    int d = g_chk_d[g];                              // uniform across warp
    float l0x = 0.0f, l0y = 0.0f, l1x = 0.0f, l1y = 0.0f;
    int c = 0;
    if (lane < d) {
        c = g_chk_mem[g * MAXD + lane];              // col-major member edge
        int v = c / 3;
        float x0 = __ldg(&llr[b0 * N_VAR + v]);
        float x1 = __ldg(&llr[b1 * N_VAR + v]);
        if (it > 0) {
            int vb = 3 * v, r = c - vb;
            int s1 = vb + ((r == 0) ? 1 : 0);        // ascending siblings
            int s2 = vb + ((r == 2) ? 1 : 2);
            const float* vp0 = g_vsr[(it - 1) & 1] + (size_t)b0 * E_EDGE;
            const float* vp1 = g_vsr[(it - 1) & 1] + (size_t)b1 * E_EDGE;
            x0 = x0 + (vp0[s1] + vp0[s2]);           // R10 v2c pairing
            x1 = x1 + (vp1[s1] + vp1[s2]);
        }
        float2 k0 = lrk_of(x0); l0x = k0.x; l0y = k0.y;
        float2 k1 = lrk_of(x1); l1x = k1.x; l1y = k1.y;
    }

    // exclude-self sums, strictly ascending member order (matmul order)
    float s0r = 0.0f, s0k = 0.0f, s1r = 0.0f, s1k = 0.0f;
    for (int q = 0; q < d; ++q) {
        float a0 = __shfl_sync(0xffffffffu, l0x, q);
        float a1 = __shfl_sync(0xffffffffu, l0y, q);
        float a2 = __shfl_sync(0xffffffffu, l1x, q);
        float a3 = __shfl_sync(0xffffffffu, l1y, q);
        if (q != lane) { s0r += a0; s0k += a1; s1r += a2; s1k += a3; }
    }

    if (lane < d) {
        float vs0 = vsr_tail(s0r, s0k);
        float vs1 = vsr_tail(s1r, s1k);
        g_vsr[it & 1][(size_t)b0 * E_EDGE + c] = vs0;
        g_vsr[it & 1][(size_t)b1 * E_EDGE + c] = vs1;
    }
}

// ---------------------------------------------------------------------------
// Kernel 5: hard decision. vsr is col-major-indexed; p_r2l ascending per
// variable => (vsr[3v] + vsr[3v+1]) + vsr[3v+2] is R10's decision order.
// Output float 0/1 (dtype lesson of round 9).
// ---------------------------------------------------------------------------
__global__ void bp_decision_kernel(const float* __restrict__ llr,
                                   const int* __restrict__ iters_p,
                                   float* __restrict__ out) {
    int iters = iters_p ? iters_p[0] : MAX_IT;
    if (iters < 1 || iters > MAX_IT) iters = MAX_IT;
    int pb = (iters - 1) & 1;

    int idx = blockIdx.x * blockDim.x + threadIdx.x;
    if (idx >= BATCH * N_VAR) return;
    int b = idx / N_VAR, v = idx - b * N_VAR;
    const float* vp = g_vsr[pb] + (size_t)b * E_EDGE;
    float T = (vp[3 * v] + vp[3 * v + 1]) + vp[3 * v + 2];
    float l = __ldg(&llr[idx]) + T;
    int sgn = (l > 0.0f) ? 1 : ((l < 0.0f) ? -1 : 0);
    out[idx] = (float)((1 - sgn) >> 1);   // 0.0f / 1.0f
}

// ---------------------------------------------------------------------------
// Inputs identified by element count (robust to ordering):
//   18432      -> llr_in [16,1152]
//   3981312 x2 -> H_x_to_xe0 [E,N] / H_xe_v_sumc_to_y [N,E]  (probed)
//   11943936x2 -> H_sumC_to_V / H_sumV_to_C [E,E]            (probed)
//   1          -> bp_iter_num int32
// Output: float32 [16, 1152] (0.0 / 1.0)
// ---------------------------------------------------------------------------
extern "C" void kernel_launch(void* const* d_in, const int* in_sizes, int n_in,
                              void* d_out, int out_size) {
    int idx_llr = -1, idx_it = -1;
    int en[2] = {-1, -1}, ee[2] = {-1, -1};
    int nen = 0, nee = 0;
    for (int i = 0; i < n_in; ++i) {
        int s = in_sizes[i];
        if (s == BATCH * N_VAR) idx_llr = i;
        else if (s == 1) idx_it = i;
        else if (s == E_EDGE * N_VAR) { if (nen < 2) en[nen] = i; nen++; }
        else if (s == E_EDGE * E_EDGE) { if (nee < 2) ee[nee] = i; nee++; }
    }
    if (idx_llr < 0) idx_llr = 0;
    if (en[0] < 0) en[0] = 1;
    if (en[1] < 0) en[1] = 4;
    if (ee[0] < 0) ee[0] = 2;
    if (ee[1] < 0) ee[1] = 3;

    const float* llr = (const float*)d_in[idx_llr];
    const float* en0 = (const float*)d_in[en[0]];
    const float* en1 = (const float*)d_in[en[1]];
    const float* ee0 = (const float*)d_in[ee[0]];
    const float* ee1 = (const float*)d_in[ee[1]];
    const int* iters = (idx_it >= 0) ? (const int*)d_in[idx_it] : (const int*)0;
    float* out = (float*)d_out;

    probe_en_kernel<<<1, 1024>>>(en0, en1);
    extract_perm_kernel<<<N_VAR, 128>>>(en0, en1);
    build_groups_kernel<<<1, 1024>>>(ee0, ee1);

    const int GW = (HBATCH * M_CHK * 32) / 256;   // 576 blocks, 4608 warps
    for (int it = 0; it < MAX_IT; ++it)
        bp_check_kernel<<<GW, 256>>>(llr, iters, it);
    bp_decision_kernel<<<(BATCH * N_VAR + 255) / 256, 256>>>(llr, iters, out);
}